// round 8
// baseline (speedup 1.0000x reference)
#include <cuda_runtime.h>
#include <cuda_fp16.h>
#include <cstdint>

// ============================================================================
// Soft-quantization codebook kernel — ldmatrix + mma.sync HMMA path.
//
// R7 -> R8 (L1/shared at 68% was the binding pipe):
//   * A operand computed DIRECTLY in mma fragment register layout
//     (no A smem tile, no zero-fill, no A ldmatrix)
//   * softmax weights via geometric recurrence (linspace anchors):
//     w(s+1) = w(s)*T, T *= Q; 5 MUFU per row at window start, 8 FMUL/step after
//   * row sums reduced with 2 shfl_xor in the quad; inv lands in the owner thread
// ============================================================================

#define MTILE    128
#define KANCH    256
#define EDIM     64
#define B_STRIDE 144                // bytes per B k-row: 64 f16 + 8 f16 pad

__device__ __forceinline__ uint32_t smem_u32(const void* p) {
    uint32_t a;
    asm("{ .reg .u64 t; cvta.to.shared.u64 t, %1; cvt.u32.u64 %0, t; }" : "=r"(a) : "l"(p));
    return a;
}

__device__ __forceinline__ float ex2f(float x) {
    float r;
    asm("ex2.approx.ftz.f32 %0, %1;" : "=f"(r) : "f"(x));
    return r;
}

#define LDMATRIX_X4T(r0, r1, r2, r3, addr)                                        \
    asm volatile("ldmatrix.sync.aligned.m8n8.x4.trans.shared.b16 {%0,%1,%2,%3}, [%4];" \
        : "=r"(r0), "=r"(r1), "=r"(r2), "=r"(r3) : "r"(addr))

#define MMA16816(c, a, b)                                                         \
    asm volatile("mma.sync.aligned.m16n8k16.row.col.f32.f16.f16.f32 "             \
        "{%0,%1,%2,%3}, {%4,%5,%6,%7}, {%8,%9}, {%0,%1,%2,%3};"                   \
        : "+f"((c)[0]), "+f"((c)[1]), "+f"((c)[2]), "+f"((c)[3])                  \
        : "r"((a)[0]), "r"((a)[1]), "r"((a)[2]), "r"((a)[3]),                     \
          "r"((b)[0]), "r"((b)[1]))

#define CVT_F16X2(d, hi, lo) \
    asm("cvt.rn.f16x2.f32 %0, %1, %2;" : "=r"(d) : "f"(hi), "f"(lo))

__global__ void __launch_bounds__(128, 2)
softquant_kernel(const float* __restrict__ xg,
                 const float* __restrict__ anchors_g,
                 const float* __restrict__ emb_g,
                 const float* __restrict__ gamma_g,
                 float* __restrict__ out_g,
                 int ntiles)
{
    __shared__ __align__(128) unsigned char sBmem[KANCH * B_STRIDE];  // 36864 B
    __shared__ float sAnch[KANCH];

    const uint32_t smB = smem_u32(sBmem);

    const int tid   = threadIdx.x;
    const int lane  = tid & 31;
    const int warp  = tid >> 5;
    const int R0    = warp * 32;
    const int group = lane >> 2;     // 0..7
    const int q     = lane & 3;      // k-slot quad index

    // ---- one-time per CTA: E f32 -> f16 smem B [K=256 rows, 144B stride] ----
    #pragma unroll
    for (int i = 0; i < 32; i++) {
        const int idx4 = tid + i * 128;
        const float4 v = reinterpret_cast<const float4*>(emb_g)[idx4];
        const int base = idx4 * 4;
        const int k = base >> 6, n = base & 63;
        uint32_t h01, h23;
        CVT_F16X2(h01, v.y, v.x);
        CVT_F16X2(h23, v.w, v.z);
        asm volatile("st.shared.v2.b32 [%0], {%1, %2};"
                     :: "r"(smB + (uint32_t)(k * B_STRIDE + n * 2)), "r"(h01), "r"(h23));
    }
    sAnch[tid]       = anchors_g[tid];
    sAnch[tid + 128] = anchors_g[tid + 128];
    __syncthreads();

    // ---- per-thread constants (hoisted out of tile loop) ----
    const float g   = fabsf(gamma_g[0]);
    const float l2e = 1.4426950408889634f;
    const float c1  = -g * l2e;                   // ex2 arg scale for -g*d^2
    const float A0  = sAnch[0];
    const float dlt = sAnch[1] - sAnch[0];
    const float rdlt = 1.0f / dlt;
    const float gd2l = g * dlt * dlt * l2e;       // g*delta^2*log2(e)
    const float m1  = 32.0f * g * dlt * l2e;      // T init: ex2(m1*(x-a_kb) + m2)
    const float m2  = -256.0f * gd2l;
    const float U1  = ex2f(-32.0f * gd2l);
    const float U8  = ex2f(-256.0f * gd2l);
    const float U9  = U8 * U1;
    const float Q   = ex2f(-512.0f * gd2l);

    // B x4.trans lane address (identical to R7): lanes 0-15 k-rows, 16-31 n-octet+1
    const uint32_t bLane = smB + (uint32_t)(lane & 15) * B_STRIDE + (uint32_t)(lane >> 4) * 16u;

    for (int tile = blockIdx.x; tile < ntiles; tile += gridDim.x) {
        // ---- per-row setup: rows j: R0 + (j>>1)*16 + (j&1)*8 + group ----
        float xv[4];
        int   s0r[4];
        int   lo = 16, hi = 0;
        #pragma unroll
        for (int j = 0; j < 4; j++) {
            const int rowLoc = R0 + ((j >> 1) << 4) + ((j & 1) << 3) + group;
            xv[j] = xg[(size_t)tile * MTILE + rowLoc];
            int i0 = __float2int_rn((xv[j] - A0) * rdlt);
            i0 = min(max(i0, 0), KANCH - 1);
            s0r[j] = max(i0 - 40, 0) >> 4;
            const int se = (min(i0 + 40, KANCH - 1) >> 4) + 1;
            lo = min(lo, s0r[j]);
            hi = max(hi, se);
        }
        // warp union of step ranges
        #pragma unroll
        for (int off = 16; off > 0; off >>= 1) {
            lo = min(lo, __shfl_xor_sync(0xffffffffu, lo, off));
            hi = max(hi, __shfl_xor_sync(0xffffffffu, hi, off));
        }

        float w[4][4];
        float T[4];
        float sums[4];
        #pragma unroll
        for (int j = 0; j < 4; j++) {
            sums[j] = 0.0f; T[j] = 0.0f;
            #pragma unroll
            for (int c = 0; c < 4; c++) w[j][c] = 0.0f;
        }

        float acc[2][8][4];
        #pragma unroll
        for (int mt = 0; mt < 2; mt++)
            #pragma unroll
            for (int nt = 0; nt < 8; nt++)
                #pragma unroll
                for (int c = 0; c < 4; c++) acc[mt][nt][c] = 0.0f;

        for (int s = lo; s < hi; s++) {
            // ---- B fragments (8 n-octets via 4 x4.trans) ----
            const uint32_t bAddr = bLane + (uint32_t)(16 * s) * B_STRIDE;
            uint32_t b[8][2];
            #pragma unroll
            for (int nt = 0; nt < 8; nt += 2)
                LDMATRIX_X4T(b[nt][0], b[nt][1], b[nt + 1][0], b[nt + 1][1],
                             bAddr + (uint32_t)(nt * 16));

            // ---- weights: recurrence in fragment layout ----
            const int kb = s * 16 + q * 2;
            const float2 aA = *reinterpret_cast<const float2*>(sAnch + kb);
            const float2 aB = *reinterpret_cast<const float2*>(sAnch + kb + 8);
            #pragma unroll
            for (int j = 0; j < 4; j++) {
                if (s == s0r[j]) {
                    const float d0 = xv[j] - aA.x, d1 = xv[j] - aA.y;
                    const float d8 = xv[j] - aB.x, d9 = xv[j] - aB.y;
                    w[j][0] = ex2f((c1 * d0) * d0);
                    w[j][1] = ex2f((c1 * d1) * d1);
                    w[j][2] = ex2f((c1 * d8) * d8);
                    w[j][3] = ex2f((c1 * d9) * d9);
                    T[j] = ex2f(m1 * d0 + m2);
                } else if (s > s0r[j]) {
                    const float f = T[j];
                    w[j][0] *= f;
                    w[j][1] *= f * U1;
                    w[j][2] *= f * U8;
                    w[j][3] *= f * U9;
                    T[j] = f * Q;
                }
                sums[j] += (w[j][0] + w[j][1]) + (w[j][2] + w[j][3]);
            }

            // ---- pack A fragments (lo half = even k, hi half = odd k) ----
            uint32_t afr[2][4];
            #pragma unroll
            for (int mt = 0; mt < 2; mt++) {
                const int j0 = mt * 2, j1 = mt * 2 + 1;
                CVT_F16X2(afr[mt][0], w[j0][1], w[j0][0]);
                CVT_F16X2(afr[mt][1], w[j1][1], w[j1][0]);
                CVT_F16X2(afr[mt][2], w[j0][3], w[j0][2]);
                CVT_F16X2(afr[mt][3], w[j1][3], w[j1][2]);
            }

            #pragma unroll
            for (int nt = 0; nt < 8; nt++) {
                MMA16816(acc[0][nt], afr[0], b[nt]);
                MMA16816(acc[1][nt], afr[1], b[nt]);
            }
        }

        // ---- row sums: reduce across the quad; result lands in owner thread ----
        #pragma unroll
        for (int j = 0; j < 4; j++) {
            sums[j] += __shfl_xor_sync(0xffffffffu, sums[j], 1);
            sums[j] += __shfl_xor_sync(0xffffffffu, sums[j], 2);
            sums[j] = 1.0f / sums[j];
        }

        // ---- epilogue ----
        #pragma unroll
        for (int mt = 0; mt < 2; mt++) {
            const float iv0 = sums[mt * 2 + 0];   // row mt*16 + group
            const float iv1 = sums[mt * 2 + 1];   // row mt*16 + group + 8
            const size_t row = (size_t)tile * MTILE + R0 + mt * 16 + group;
            #pragma unroll
            for (int nt = 0; nt < 8; nt++) {
                float* o = out_g + row * EDIM + nt * 8 + q * 2;
                float2 v0, v1;
                v0.x = acc[mt][nt][0] * iv0;  v0.y = acc[mt][nt][1] * iv0;
                v1.x = acc[mt][nt][2] * iv1;  v1.y = acc[mt][nt][3] * iv1;
                *reinterpret_cast<float2*>(o)            = v0;   // row
                *reinterpret_cast<float2*>(o + 8 * EDIM) = v1;   // row + 8
            }
        }
    }
}

extern "C" void kernel_launch(void* const* d_in, const int* in_sizes, int n_in,
                              void* d_out, int out_size) {
    const float* x       = (const float*)d_in[0];
    const float* anchors = (const float*)d_in[1];
    const float* emb     = (const float*)d_in[2];
    const float* gamma   = (const float*)d_in[3];
    float* out = (float*)d_out;

    const int rows   = in_sizes[0];          // 262144
    const int ntiles = rows / MTILE;         // 2048

    int dev = 0, nsm = 148;
    cudaGetDevice(&dev);
    cudaDeviceGetAttribute(&nsm, cudaDevAttrMultiProcessorCount, dev);
    int grid = 2 * nsm;                      // persistent: 2 CTAs per SM
    if (grid > ntiles) grid = ntiles;

    softquant_kernel<<<grid, MTILE>>>(x, anchors, emb, gamma, out, ntiles);
}

// round 9
// speedup vs baseline: 1.2700x; 1.2700x over previous
#include <cuda_runtime.h>
#include <cuda_fp16.h>
#include <cstdint>

// ============================================================================
// Soft-quantization codebook kernel — ldmatrix + mma.sync HMMA path.
//
// R8 -> R9 (issue/latency-bound at 8 warps/SM, branchy recurrence):
//   * branch-free recurrence: per-row init hoisted pre-loop, in-loop FSEL inject
//   * row sums computed BY the MMA: B widened to 72 cols, col 64 = 1.0
//     (9th n-octet) -> D[:,64] = sum(w); scalar sum work deleted
//   * occupancy 2 -> 3 CTAs/SM (launch_bounds(128,3), grid = 3*SMs)
// ============================================================================

#define MTILE    128
#define KANCH    256
#define EDIM     64
#define B_STRIDE 144                // bytes per B k-row: 72 f16 (64 E + ones col + zeros)

__device__ __forceinline__ uint32_t smem_u32(const void* p) {
    uint32_t a;
    asm("{ .reg .u64 t; cvta.to.shared.u64 t, %1; cvt.u32.u64 %0, t; }" : "=r"(a) : "l"(p));
    return a;
}

__device__ __forceinline__ float ex2f(float x) {
    float r;
    asm("ex2.approx.ftz.f32 %0, %1;" : "=f"(r) : "f"(x));
    return r;
}

#define LDMATRIX_X4T(r0, r1, r2, r3, addr)                                        \
    asm volatile("ldmatrix.sync.aligned.m8n8.x4.trans.shared.b16 {%0,%1,%2,%3}, [%4];" \
        : "=r"(r0), "=r"(r1), "=r"(r2), "=r"(r3) : "r"(addr))

#define LDMATRIX_X2T(r0, r1, addr)                                                \
    asm volatile("ldmatrix.sync.aligned.m8n8.x2.trans.shared.b16 {%0,%1}, [%2];"  \
        : "=r"(r0), "=r"(r1) : "r"(addr))

#define MMA16816(c, a, b)                                                         \
    asm volatile("mma.sync.aligned.m16n8k16.row.col.f32.f16.f16.f32 "             \
        "{%0,%1,%2,%3}, {%4,%5,%6,%7}, {%8,%9}, {%0,%1,%2,%3};"                   \
        : "+f"((c)[0]), "+f"((c)[1]), "+f"((c)[2]), "+f"((c)[3])                  \
        : "r"((a)[0]), "r"((a)[1]), "r"((a)[2]), "r"((a)[3]),                     \
          "r"((b)[0]), "r"((b)[1]))

#define CVT_F16X2(d, hi, lo) \
    asm("cvt.rn.f16x2.f32 %0, %1, %2;" : "=r"(d) : "f"(hi), "f"(lo))

__global__ void __launch_bounds__(128, 3)
softquant_kernel(const float* __restrict__ xg,
                 const float* __restrict__ anchors_g,
                 const float* __restrict__ emb_g,
                 const float* __restrict__ gamma_g,
                 float* __restrict__ out_g,
                 int ntiles)
{
    __shared__ __align__(128) unsigned char sBmem[KANCH * B_STRIDE];  // 36864 B
    __shared__ float sAnch[KANCH];

    const uint32_t smB = smem_u32(sBmem);

    const int tid   = threadIdx.x;
    const int lane  = tid & 31;
    const int warp  = tid >> 5;
    const int R0    = warp * 32;
    const int group = lane >> 2;     // 0..7
    const int q     = lane & 3;      // k-slot quad index

    // ---- one-time per CTA: E f32 -> f16 smem B cols 0..63 ----
    #pragma unroll
    for (int i = 0; i < 32; i++) {
        const int idx4 = tid + i * 128;
        const float4 v = reinterpret_cast<const float4*>(emb_g)[idx4];
        const int base = idx4 * 4;
        const int k = base >> 6, n = base & 63;
        uint32_t h01, h23;
        CVT_F16X2(h01, v.y, v.x);
        CVT_F16X2(h23, v.w, v.z);
        asm volatile("st.shared.v2.b32 [%0], {%1, %2};"
                     :: "r"(smB + (uint32_t)(k * B_STRIDE + n * 2)), "r"(h01), "r"(h23));
    }
    // cols 64..71: col64 = 1.0h (sum column), rest 0
    for (int k = tid; k < KANCH; k += 128)
        asm volatile("st.shared.v4.b32 [%0], {%1,%2,%2,%2};"
                     :: "r"(smB + (uint32_t)(k * B_STRIDE + 128)), "r"(0x00003C00u), "r"(0u));
    sAnch[tid]       = anchors_g[tid];
    sAnch[tid + 128] = anchors_g[tid + 128];
    __syncthreads();

    // ---- per-thread constants ----
    const float g    = fabsf(gamma_g[0]);
    const float l2e  = 1.4426950408889634f;
    const float c1   = -g * l2e;
    const float A0   = sAnch[0];
    const float dlt  = sAnch[1] - sAnch[0];
    const float rdlt = 1.0f / dlt;
    const float gd2l = g * dlt * dlt * l2e;
    const float m1   = 32.0f * g * dlt * l2e;
    const float m2   = -256.0f * gd2l;
    const float U1   = ex2f(-32.0f * gd2l);
    const float U8   = ex2f(-256.0f * gd2l);
    const float U9   = U8 * U1;
    const float Q    = ex2f(-512.0f * gd2l);

    const uint32_t bLane16 = smB + (uint32_t)(lane & 15) * B_STRIDE;
    const uint32_t bLane   = bLane16 + (uint32_t)(lane >> 4) * 16u;

    for (int tile = blockIdx.x; tile < ntiles; tile += gridDim.x) {
        // ---- per-row setup + hoisted recurrence init ----
        float xv[4], wi[4][4], w[4][4], T[4];
        int   s0r[4];
        int   lo = 16, hi = 0;
        #pragma unroll
        for (int j = 0; j < 4; j++) {
            const int rowLoc = R0 + ((j >> 1) << 4) + ((j & 1) << 3) + group;
            xv[j] = xg[(size_t)tile * MTILE + rowLoc];
            int i0 = __float2int_rn((xv[j] - A0) * rdlt);
            i0 = min(max(i0, 0), KANCH - 1);
            s0r[j] = max(i0 - 40, 0) >> 4;
            const int se = (min(i0 + 40, KANCH - 1) >> 4) + 1;
            lo = min(lo, s0r[j]);
            hi = max(hi, se);

            const int kb0 = s0r[j] * 16 + q * 2;
            const float2 aA = *reinterpret_cast<const float2*>(sAnch + kb0);
            const float2 aB = *reinterpret_cast<const float2*>(sAnch + kb0 + 8);
            const float d0 = xv[j] - aA.x, d1 = xv[j] - aA.y;
            const float d8 = xv[j] - aB.x, d9 = xv[j] - aB.y;
            wi[j][0] = ex2f((c1 * d0) * d0);
            wi[j][1] = ex2f((c1 * d1) * d1);
            wi[j][2] = ex2f((c1 * d8) * d8);
            wi[j][3] = ex2f((c1 * d9) * d9);
            T[j]     = ex2f(m1 * d0 + m2);
            w[j][0] = 0.0f; w[j][1] = 0.0f; w[j][2] = 0.0f; w[j][3] = 0.0f;
        }
        // warp union of step ranges
        #pragma unroll
        for (int off = 16; off > 0; off >>= 1) {
            lo = min(lo, __shfl_xor_sync(0xffffffffu, lo, off));
            hi = max(hi, __shfl_xor_sync(0xffffffffu, hi, off));
        }

        float acc[2][9][4];
        #pragma unroll
        for (int mt = 0; mt < 2; mt++)
            #pragma unroll
            for (int nt = 0; nt < 9; nt++)
                #pragma unroll
                for (int c = 0; c < 4; c++) acc[mt][nt][c] = 0.0f;

        for (int s = lo; s < hi; s++) {
            // ---- B fragments: 8 E-octets + sum octet ----
            const uint32_t bRow = (uint32_t)(16 * s) * B_STRIDE;
            uint32_t b[9][2];
            #pragma unroll
            for (int nt = 0; nt < 8; nt += 2)
                LDMATRIX_X4T(b[nt][0], b[nt][1], b[nt + 1][0], b[nt + 1][1],
                             bLane + bRow + (uint32_t)(nt * 16));
            LDMATRIX_X2T(b[8][0], b[8][1], bLane16 + bRow + 128u);

            // ---- weights: branch-free recurrence (FSEL inject, no BSSY) ----
            #pragma unroll
            for (int j = 0; j < 4; j++) {
                const bool isInit  = (s == s0r[j]);
                const bool isAfter = (s > s0r[j]);
                const float f  = T[j];
                const float w0 = w[j][0] * f;
                const float w1 = w[j][1] * (f * U1);
                const float w2 = w[j][2] * (f * U8);
                const float w3 = w[j][3] * (f * U9);
                w[j][0] = isInit ? wi[j][0] : w0;
                w[j][1] = isInit ? wi[j][1] : w1;
                w[j][2] = isInit ? wi[j][2] : w2;
                w[j][3] = isInit ? wi[j][3] : w3;
                T[j]    = isAfter ? f * Q : f;
            }

            // ---- pack A fragments ----
            uint32_t afr[2][4];
            #pragma unroll
            for (int mt = 0; mt < 2; mt++) {
                const int j0 = mt * 2, j1 = mt * 2 + 1;
                CVT_F16X2(afr[mt][0], w[j0][1], w[j0][0]);
                CVT_F16X2(afr[mt][1], w[j1][1], w[j1][0]);
                CVT_F16X2(afr[mt][2], w[j0][3], w[j0][2]);
                CVT_F16X2(afr[mt][3], w[j1][3], w[j1][2]);
            }

            #pragma unroll
            for (int nt = 0; nt < 9; nt++) {
                MMA16816(acc[0][nt], afr[0], b[nt]);
                MMA16816(acc[1][nt], afr[1], b[nt]);
            }
        }

        // ---- row inverse-sums from the sum column (col 64, q==0, c0/c2) ----
        const int srcLane = lane & ~3;
        float iv[4];
        iv[0] = __shfl_sync(0xffffffffu, 1.0f / acc[0][8][0], srcLane);  // row group
        iv[1] = __shfl_sync(0xffffffffu, 1.0f / acc[0][8][2], srcLane);  // row group+8
        iv[2] = __shfl_sync(0xffffffffu, 1.0f / acc[1][8][0], srcLane);  // row group+16
        iv[3] = __shfl_sync(0xffffffffu, 1.0f / acc[1][8][2], srcLane);  // row group+24

        // ---- epilogue ----
        #pragma unroll
        for (int mt = 0; mt < 2; mt++) {
            const float iv0 = iv[mt * 2 + 0];
            const float iv1 = iv[mt * 2 + 1];
            const size_t row = (size_t)tile * MTILE + R0 + mt * 16 + group;
            #pragma unroll
            for (int nt = 0; nt < 8; nt++) {
                float* o = out_g + row * EDIM + nt * 8 + q * 2;
                float2 v0, v1;
                v0.x = acc[mt][nt][0] * iv0;  v0.y = acc[mt][nt][1] * iv0;
                v1.x = acc[mt][nt][2] * iv1;  v1.y = acc[mt][nt][3] * iv1;
                *reinterpret_cast<float2*>(o)            = v0;   // row
                *reinterpret_cast<float2*>(o + 8 * EDIM) = v1;   // row + 8
            }
        }
    }
}

extern "C" void kernel_launch(void* const* d_in, const int* in_sizes, int n_in,
                              void* d_out, int out_size) {
    const float* x       = (const float*)d_in[0];
    const float* anchors = (const float*)d_in[1];
    const float* emb     = (const float*)d_in[2];
    const float* gamma   = (const float*)d_in[3];
    float* out = (float*)d_out;

    const int rows   = in_sizes[0];          // 262144
    const int ntiles = rows / MTILE;         // 2048

    int dev = 0, nsm = 148;
    cudaGetDevice(&dev);
    cudaDeviceGetAttribute(&nsm, cudaDevAttrMultiProcessorCount, dev);
    int grid = 3 * nsm;                      // persistent: 3 CTAs per SM
    if (grid > ntiles) grid = ntiles;

    softquant_kernel<<<grid, MTILE>>>(x, anchors, emb, gamma, out, ntiles);
}

// round 10
// speedup vs baseline: 1.3477x; 1.0611x over previous
#include <cuda_runtime.h>
#include <cuda_fp16.h>
#include <cstdint>

// ============================================================================
// Soft-quantization codebook kernel — ldmatrix + mma.sync HMMA path.
//
// R9 -> R10 (issue-bound; warp step-range = union of 32 scattered windows):
//   * per-tile counting-sort of the 128 rows by anchor index; warp w takes
//     sorted ranks 32w..32w+31  ->  warp window union drops ~11.5 -> ~7.5 steps
//   * epilogue writes through the row permutation (explicit per-row addresses)
//   * everything else identical to R9 (FSEL recurrence, MMA sum column, occ 3)
// ============================================================================

#define MTILE    128
#define KANCH    256
#define EDIM     64
#define B_STRIDE 144                // bytes per B k-row: 72 f16 (64 E + ones col + zeros)

__device__ __forceinline__ uint32_t smem_u32(const void* p) {
    uint32_t a;
    asm("{ .reg .u64 t; cvta.to.shared.u64 t, %1; cvt.u32.u64 %0, t; }" : "=r"(a) : "l"(p));
    return a;
}

__device__ __forceinline__ float ex2f(float x) {
    float r;
    asm("ex2.approx.ftz.f32 %0, %1;" : "=f"(r) : "f"(x));
    return r;
}

#define LDMATRIX_X4T(r0, r1, r2, r3, addr)                                        \
    asm volatile("ldmatrix.sync.aligned.m8n8.x4.trans.shared.b16 {%0,%1,%2,%3}, [%4];" \
        : "=r"(r0), "=r"(r1), "=r"(r2), "=r"(r3) : "r"(addr))

#define LDMATRIX_X2T(r0, r1, addr)                                                \
    asm volatile("ldmatrix.sync.aligned.m8n8.x2.trans.shared.b16 {%0,%1}, [%2];"  \
        : "=r"(r0), "=r"(r1) : "r"(addr))

#define MMA16816(c, a, b)                                                         \
    asm volatile("mma.sync.aligned.m16n8k16.row.col.f32.f16.f16.f32 "             \
        "{%0,%1,%2,%3}, {%4,%5,%6,%7}, {%8,%9}, {%0,%1,%2,%3};"                   \
        : "+f"((c)[0]), "+f"((c)[1]), "+f"((c)[2]), "+f"((c)[3])                  \
        : "r"((a)[0]), "r"((a)[1]), "r"((a)[2]), "r"((a)[3]),                     \
          "r"((b)[0]), "r"((b)[1]))

#define CVT_F16X2(d, hi, lo) \
    asm("cvt.rn.f16x2.f32 %0, %1, %2;" : "=r"(d) : "f"(hi), "f"(lo))

__global__ void __launch_bounds__(128, 3)
softquant_kernel(const float* __restrict__ xg,
                 const float* __restrict__ anchors_g,
                 const float* __restrict__ emb_g,
                 const float* __restrict__ gamma_g,
                 float* __restrict__ out_g,
                 int ntiles)
{
    __shared__ __align__(128) unsigned char sBmem[KANCH * B_STRIDE];  // 36864 B
    __shared__ float sAnch[KANCH];
    __shared__ int   sHist[KANCH];      // sort histogram / prefix
    __shared__ float sXs[MTILE];        // sorted x values
    __shared__ int   sRow[MTILE];       // sorted rank -> original row
    __shared__ int   sWS[4];            // per-warp scan totals

    const uint32_t smB = smem_u32(sBmem);

    const int tid   = threadIdx.x;
    const int lane  = tid & 31;
    const int warp  = tid >> 5;
    const int R0    = warp * 32;
    const int group = lane >> 2;     // 0..7
    const int q     = lane & 3;      // k-slot quad index

    // ---- one-time per CTA: E f32 -> f16 smem B cols 0..63 ----
    #pragma unroll
    for (int i = 0; i < 32; i++) {
        const int idx4 = tid + i * 128;
        const float4 v = reinterpret_cast<const float4*>(emb_g)[idx4];
        const int base = idx4 * 4;
        const int k = base >> 6, n = base & 63;
        uint32_t h01, h23;
        CVT_F16X2(h01, v.y, v.x);
        CVT_F16X2(h23, v.w, v.z);
        asm volatile("st.shared.v2.b32 [%0], {%1, %2};"
                     :: "r"(smB + (uint32_t)(k * B_STRIDE + n * 2)), "r"(h01), "r"(h23));
    }
    // cols 64..71: col64 = 1.0h (sum column), rest 0
    for (int k = tid; k < KANCH; k += 128)
        asm volatile("st.shared.v4.b32 [%0], {%1,%2,%2,%2};"
                     :: "r"(smB + (uint32_t)(k * B_STRIDE + 128)), "r"(0x00003C00u), "r"(0u));
    sAnch[tid]       = anchors_g[tid];
    sAnch[tid + 128] = anchors_g[tid + 128];
    __syncthreads();

    // ---- per-thread constants ----
    const float g    = fabsf(gamma_g[0]);
    const float l2e  = 1.4426950408889634f;
    const float c1   = -g * l2e;
    const float A0   = sAnch[0];
    const float dlt  = sAnch[1] - sAnch[0];
    const float rdlt = 1.0f / dlt;
    const float gd2l = g * dlt * dlt * l2e;
    const float m1   = 32.0f * g * dlt * l2e;
    const float m2   = -256.0f * gd2l;
    const float U1   = ex2f(-32.0f * gd2l);
    const float U8   = ex2f(-256.0f * gd2l);
    const float U9   = U8 * U1;
    const float Q    = ex2f(-512.0f * gd2l);

    const uint32_t bLane16 = smB + (uint32_t)(lane & 15) * B_STRIDE;
    const uint32_t bLane   = bLane16 + (uint32_t)(lane >> 4) * 16u;

    for (int tile = blockIdx.x; tile < ntiles; tile += gridDim.x) {
        // ================= counting sort of rows by anchor index =================
        sHist[tid] = 0;
        sHist[tid + 128] = 0;
        __syncthreads();
        const float xv0 = xg[(size_t)tile * MTILE + tid];
        int i0t = __float2int_rn((xv0 - A0) * rdlt);
        i0t = min(max(i0t, 0), KANCH - 1);
        const int localOff = atomicAdd(&sHist[i0t], 1);
        __syncthreads();
        {   // exclusive prefix scan over 256 bins (2 bins/thread + warp shfl scan)
            const int a = sHist[2 * tid], b = sHist[2 * tid + 1];
            const int sv = a + b;
            int incl = sv;
            #pragma unroll
            for (int off = 1; off < 32; off <<= 1) {
                const int n = __shfl_up_sync(0xffffffffu, incl, off);
                if (lane >= off) incl += n;
            }
            if (lane == 31) sWS[warp] = incl;
            __syncthreads();
            int wbase = 0;
            #pragma unroll
            for (int wj = 0; wj < 4; wj++) wbase += (wj < warp) ? sWS[wj] : 0;
            const int exclA = wbase + incl - sv;
            sHist[2 * tid]     = exclA;
            sHist[2 * tid + 1] = exclA + a;
        }
        __syncthreads();
        const int rank = sHist[i0t] + localOff;
        sXs[rank]  = xv0;
        sRow[rank] = tid;
        __syncthreads();

        // ---- per-row setup + hoisted recurrence init (rows = sorted ranks) ----
        float xv[4], wi[4][4], w[4][4], T[4];
        int   s0r[4], rowOf[4];
        int   lo = 16, hi = 0;
        #pragma unroll
        for (int j = 0; j < 4; j++) {
            const int rk = R0 + ((j >> 1) << 4) + ((j & 1) << 3) + group;
            xv[j]    = sXs[rk];
            rowOf[j] = sRow[rk];
            int i0 = __float2int_rn((xv[j] - A0) * rdlt);
            i0 = min(max(i0, 0), KANCH - 1);
            s0r[j] = max(i0 - 40, 0) >> 4;
            const int se = (min(i0 + 40, KANCH - 1) >> 4) + 1;
            lo = min(lo, s0r[j]);
            hi = max(hi, se);

            const int kb0 = s0r[j] * 16 + q * 2;
            const float2 aA = *reinterpret_cast<const float2*>(sAnch + kb0);
            const float2 aB = *reinterpret_cast<const float2*>(sAnch + kb0 + 8);
            const float d0 = xv[j] - aA.x, d1 = xv[j] - aA.y;
            const float d8 = xv[j] - aB.x, d9 = xv[j] - aB.y;
            wi[j][0] = ex2f((c1 * d0) * d0);
            wi[j][1] = ex2f((c1 * d1) * d1);
            wi[j][2] = ex2f((c1 * d8) * d8);
            wi[j][3] = ex2f((c1 * d9) * d9);
            T[j]     = ex2f(m1 * d0 + m2);
            w[j][0] = 0.0f; w[j][1] = 0.0f; w[j][2] = 0.0f; w[j][3] = 0.0f;
        }
        // warp union of step ranges (sorted rows -> tight union)
        #pragma unroll
        for (int off = 16; off > 0; off >>= 1) {
            lo = min(lo, __shfl_xor_sync(0xffffffffu, lo, off));
            hi = max(hi, __shfl_xor_sync(0xffffffffu, hi, off));
        }

        float acc[2][9][4];
        #pragma unroll
        for (int mt = 0; mt < 2; mt++)
            #pragma unroll
            for (int nt = 0; nt < 9; nt++)
                #pragma unroll
                for (int c = 0; c < 4; c++) acc[mt][nt][c] = 0.0f;

        for (int s = lo; s < hi; s++) {
            // ---- B fragments: 8 E-octets + sum octet ----
            const uint32_t bRow = (uint32_t)(16 * s) * B_STRIDE;
            uint32_t b[9][2];
            #pragma unroll
            for (int nt = 0; nt < 8; nt += 2)
                LDMATRIX_X4T(b[nt][0], b[nt][1], b[nt + 1][0], b[nt + 1][1],
                             bLane + bRow + (uint32_t)(nt * 16));
            LDMATRIX_X2T(b[8][0], b[8][1], bLane16 + bRow + 128u);

            // ---- weights: branch-free recurrence (FSEL inject, no BSSY) ----
            #pragma unroll
            for (int j = 0; j < 4; j++) {
                const bool isInit  = (s == s0r[j]);
                const bool isAfter = (s > s0r[j]);
                const float f  = T[j];
                const float w0 = w[j][0] * f;
                const float w1 = w[j][1] * (f * U1);
                const float w2 = w[j][2] * (f * U8);
                const float w3 = w[j][3] * (f * U9);
                w[j][0] = isInit ? wi[j][0] : w0;
                w[j][1] = isInit ? wi[j][1] : w1;
                w[j][2] = isInit ? wi[j][2] : w2;
                w[j][3] = isInit ? wi[j][3] : w3;
                T[j]    = isAfter ? f * Q : f;
            }

            // ---- pack A fragments ----
            uint32_t afr[2][4];
            #pragma unroll
            for (int mt = 0; mt < 2; mt++) {
                const int j0 = mt * 2, j1 = mt * 2 + 1;
                CVT_F16X2(afr[mt][0], w[j0][1], w[j0][0]);
                CVT_F16X2(afr[mt][1], w[j1][1], w[j1][0]);
                CVT_F16X2(afr[mt][2], w[j0][3], w[j0][2]);
                CVT_F16X2(afr[mt][3], w[j1][3], w[j1][2]);
            }

            #pragma unroll
            for (int nt = 0; nt < 9; nt++) {
                MMA16816(acc[0][nt], afr[0], b[nt]);
                MMA16816(acc[1][nt], afr[1], b[nt]);
            }
        }

        // ---- row inverse-sums from the sum column (col 64, q==0, c0/c2) ----
        const int srcLane = lane & ~3;
        float iv[4];
        iv[0] = __shfl_sync(0xffffffffu, 1.0f / acc[0][8][0], srcLane);  // rank R0+group
        iv[1] = __shfl_sync(0xffffffffu, 1.0f / acc[0][8][2], srcLane);  // +8
        iv[2] = __shfl_sync(0xffffffffu, 1.0f / acc[1][8][0], srcLane);  // +16
        iv[3] = __shfl_sync(0xffffffffu, 1.0f / acc[1][8][2], srcLane);  // +24

        // ---- epilogue: write through the row permutation ----
        const size_t outTile = (size_t)tile * MTILE;
        #pragma unroll
        for (int mt = 0; mt < 2; mt++) {
            const float iv0 = iv[mt * 2 + 0];
            const float iv1 = iv[mt * 2 + 1];
            float* oLo = out_g + (outTile + rowOf[mt * 2 + 0]) * EDIM + q * 2;
            float* oHi = out_g + (outTile + rowOf[mt * 2 + 1]) * EDIM + q * 2;
            #pragma unroll
            for (int nt = 0; nt < 8; nt++) {
                float2 v0, v1;
                v0.x = acc[mt][nt][0] * iv0;  v0.y = acc[mt][nt][1] * iv0;
                v1.x = acc[mt][nt][2] * iv1;  v1.y = acc[mt][nt][3] * iv1;
                *reinterpret_cast<float2*>(oLo + nt * 8) = v0;
                *reinterpret_cast<float2*>(oHi + nt * 8) = v1;
            }
        }
        // next tile's sort phase begins with __syncthreads-protected writes,
        // so no extra barrier is needed here.
    }
}

extern "C" void kernel_launch(void* const* d_in, const int* in_sizes, int n_in,
                              void* d_out, int out_size) {
    const float* x       = (const float*)d_in[0];
    const float* anchors = (const float*)d_in[1];
    const float* emb     = (const float*)d_in[2];
    const float* gamma   = (const float*)d_in[3];
    float* out = (float*)d_out;

    const int rows   = in_sizes[0];          // 262144
    const int ntiles = rows / MTILE;         // 2048

    int dev = 0, nsm = 148;
    cudaGetDevice(&dev);
    cudaDeviceGetAttribute(&nsm, cudaDevAttrMultiProcessorCount, dev);
    int grid = 3 * nsm;                      // persistent: 3 CTAs per SM
    if (grid > ntiles) grid = ntiles;

    softquant_kernel<<<grid, MTILE>>>(x, anchors, emb, gamma, out, ntiles);
}